// round 16
// baseline (speedup 1.0000x reference)
#include <cuda_runtime.h>

#define N_PATHS   8
#define N_FEAT    128
#define CART      3
#define N_SPECIES 10
#define ROW_F4    1024          // 4096 floats per x row = 1024 float4
#define OUT_F4    96            // 384 floats per out row = 96 float4
#define TPB       384           // 12 warps = 4 atom-slots of 96 lanes
#define SLOTS     4             // atoms per CTA per iteration
#define LPA       96            // lanes per atom (3 full warps per atom)

__global__ __launch_bounds__(TPB, 3)   // 56-reg cap: room for 8 in-flight float4
void wps_kernel(const float4* __restrict__ x,
                const float*  __restrict__ y,
                const float*  __restrict__ w,
                float4* __restrict__ out,
                int n_atoms)
{
    const int slot = threadIdx.x / LPA;    // 0..3 : which atom in the group
    const int lane = threadIdx.x % LPA;    // 0..95: which float4 of the output
    const int wl   = threadIdx.x & 31;     // lane within warp

    // the 4 output elements e = 4*lane .. 4*lane+3 span exactly 2 features
    const int e0 = lane * 4;
    const int f0 = e0 / CART;              // first feature
    const int r  = e0 - f0 * CART;         // e0 % 3, fixed per thread

    const int stride_atoms = gridDim.x * SLOTS;

    for (int a = blockIdx.x * SLOTS + slot; a < n_atoms; a += stride_atoms) {
        const float4* xrow = x + (size_t)a * ROW_F4;

        // ---- PHASE 1: front-batch ALL 8 x loads (4 KB in flight per warp) ----
        float4 xv[N_PATHS];
        #pragma unroll
        for (int p = 0; p < N_PATHS; ++p)
            xv[p] = __ldcs(&xrow[p * LPA + lane]);   // streaming read-once

        // ---- species via warp ballot (overlaps with in-flight x loads) ----
        const float* yrow = y + (size_t)a * N_SPECIES;
        float yv = (wl < N_SPECIES) ? __ldcs(&yrow[wl]) : 0.0f;
        unsigned m = __ballot_sync(0xffffffffu, yv > 0.5f);
        const int s = __ffs(m) - 1;

        const float* wsp = w + s * (N_PATHS * N_FEAT) + f0;  // 40 KB, L1-resident

        // ---- PHASE 2: FMA drain ----
        float4 acc = {0.f, 0.f, 0.f, 0.f};
        #pragma unroll
        for (int p = 0; p < N_PATHS; ++p) {
            float wa = __ldg(&wsp[p * N_FEAT]);
            float wb = __ldg(&wsp[p * N_FEAT + 1]);
            // r=0: (wa,wa,wa,wb)  r=1: (wa,wa,wb,wb)  r=2: (wa,wb,wb,wb)
            float wy = (r == 2) ? wb : wa;
            float wz = (r == 0) ? wa : wb;
            acc.x = fmaf(xv[p].x, wa, acc.x);
            acc.y = fmaf(xv[p].y, wy, acc.y);
            acc.z = fmaf(xv[p].z, wz, acc.z);
            acc.w = fmaf(xv[p].w, wb, acc.w);
        }

        __stcs(&out[(size_t)a * OUT_F4 + lane], acc);
    }
}

extern "C" void kernel_launch(void* const* d_in, const int* in_sizes, int n_in,
                              void* d_out, int out_size)
{
    const float4* x = (const float4*)d_in[0];   // [N, 4096] fp32
    const float*  y = (const float*) d_in[1];   // [N, 10] one-hot
    const float*  w = (const float*) d_in[2];   // [10, 8, 128] fp32
    float4* out = (float4*)d_out;               // [N, 384] fp32

    const int n_atoms = in_sizes[0] / 4096;

    int grid = 148 * 3;                          // 3 CTAs/SM, even placement
    int max_grid = (n_atoms + SLOTS - 1) / SLOTS;
    if (grid > max_grid) grid = max_grid;

    wps_kernel<<<grid, TPB>>>(x, y, w, out, n_atoms);
}

// round 17
// speedup vs baseline: 1.0044x; 1.0044x over previous
#include <cuda_runtime.h>

#define N_PATHS   8
#define N_FEAT    128
#define CART      3
#define N_SPECIES 10
#define ROW_F4    1024          // 4096 floats per x row = 1024 float4
#define OUT_F4    96            // 384 floats per out row = 96 float4
#define TPB       384           // 12 warps = 4 atom-slots of 96 lanes
#define SLOTS     4             // atoms per CTA per iteration
#define LPA       96            // lanes per atom (3 full warps per atom)

__global__ __launch_bounds__(TPB, 3)   // 56-reg cap: room for 8 in-flight float4
void wps_kernel(const float4* __restrict__ x,
                const float*  __restrict__ y,
                const float*  __restrict__ w,
                float4* __restrict__ out,
                int n_atoms)
{
    const int slot = threadIdx.x / LPA;    // 0..3 : which atom in the group
    const int lane = threadIdx.x % LPA;    // 0..95: which float4 of the output
    const int wl   = threadIdx.x & 31;     // lane within warp

    // the 4 output elements e = 4*lane .. 4*lane+3 span exactly 2 features
    const int e0 = lane * 4;
    const int f0 = e0 / CART;              // first feature
    const int r  = e0 - f0 * CART;         // e0 % 3, fixed per thread

    const int stride_atoms = gridDim.x * SLOTS;

    for (int a = blockIdx.x * SLOTS + slot; a < n_atoms; a += stride_atoms) {
        const float4* xrow = x + (size_t)a * ROW_F4;

        // ---- PHASE 1: front-batch ALL 8 x loads (4 KB in flight per warp) ----
        float4 xv[N_PATHS];
        #pragma unroll
        for (int p = 0; p < N_PATHS; ++p)
            xv[p] = __ldcs(&xrow[p * LPA + lane]);   // streaming read-once

        // ---- species via warp ballot (overlaps with in-flight x loads) ----
        const float* yrow = y + (size_t)a * N_SPECIES;
        float yv = (wl < N_SPECIES) ? __ldcs(&yrow[wl]) : 0.0f;
        unsigned m = __ballot_sync(0xffffffffu, yv > 0.5f);
        const int s = __ffs(m) - 1;

        const float* wsp = w + s * (N_PATHS * N_FEAT) + f0;  // 40 KB, L1-resident

        // ---- PHASE 2: FMA drain ----
        float4 acc = {0.f, 0.f, 0.f, 0.f};
        #pragma unroll
        for (int p = 0; p < N_PATHS; ++p) {
            float wa = __ldg(&wsp[p * N_FEAT]);
            float wb = __ldg(&wsp[p * N_FEAT + 1]);
            // r=0: (wa,wa,wa,wb)  r=1: (wa,wa,wb,wb)  r=2: (wa,wb,wb,wb)
            float wy = (r == 2) ? wb : wa;
            float wz = (r == 0) ? wa : wb;
            acc.x = fmaf(xv[p].x, wa, acc.x);
            acc.y = fmaf(xv[p].y, wy, acc.y);
            acc.z = fmaf(xv[p].z, wz, acc.z);
            acc.w = fmaf(xv[p].w, wb, acc.w);
        }

        __stcs(&out[(size_t)a * OUT_F4 + lane], acc);
    }
}

extern "C" void kernel_launch(void* const* d_in, const int* in_sizes, int n_in,
                              void* d_out, int out_size)
{
    const float4* x = (const float4*)d_in[0];   // [N, 4096] fp32
    const float*  y = (const float*) d_in[1];   // [N, 10] one-hot
    const float*  w = (const float*) d_in[2];   // [10, 8, 128] fp32
    float4* out = (float4*)d_out;               // [N, 384] fp32

    const int n_atoms = in_sizes[0] / 4096;

    int grid = 148 * 3;                          // 3 CTAs/SM, even placement
    int max_grid = (n_atoms + SLOTS - 1) / SLOTS;
    if (grid > max_grid) grid = max_grid;

    wps_kernel<<<grid, TPB>>>(x, y, w, out, n_atoms);
}